// round 17
// baseline (speedup 1.0000x reference)
#include <cuda_runtime.h>
#include <cstdint>

#define Bx 2
#define Nx 32
#define Cx 128
#define Px 8192
#define NB 64
#define G3x 8
#define NEGV (-1e30f)
#define GRIDX 512

// Scratch (static device globals — allowed)
__device__ float    g_featT[(size_t)Bx * Px * Cx];  // transposed features [b][p][c]
__device__ int      g_list[NB * Px];                // per-box GLOBALLY ORDERED index list
__device__ unsigned g_bar = 0;                      // barrier arrival counter
__device__ unsigned g_rel = 0;                      // barrier release epoch

__device__ __forceinline__ uint32_t smem_u32(const void* p) {
    uint32_t a;
    asm("{ .reg .u64 t; cvta.to.shared.u64 t, %1; cvt.u32.u64 %0, t; }"
        : "=r"(a) : "l"(p));
    return a;
}
__device__ __forceinline__ void st_shared_cluster_u32(uint32_t laddr, int rank, int val) {
    asm volatile(
        "{ .reg .b32 r; mapa.shared::cluster.u32 r, %0, %1; "
        "st.shared::cluster.u32 [r], %2; }"
        :: "r"(laddr), "r"(rank), "r"(val) : "memory");
}

// ---------------------------------------------------------------------------
// One kernel, 512 CTAs, cluster = 8 bins of one box.
//  Pre-barrier: R10 transpose (strided quarters) + segment-k compaction;
//    tots exchanged via DSMEM + cluster.sync -> each CTA writes its indices
//    into the box-global ORDERED list and holds cnt/st/en in registers.
//  Grid barrier (epoch flag, R15).
//  Post-barrier: ONE contiguous coalesced g_list read -> smem -> gather-max.
// ---------------------------------------------------------------------------
__global__ void __launch_bounds__(256, 4) __cluster_dims__(8, 1, 1)
roipool_fused_kernel(
    const float* __restrict__ feat,    // [B][C][P]
    const float* __restrict__ boxes,   // [B][N][6]
    const int*   __restrict__ offset,  // [B]
    const float* __restrict__ pc,      // [B][P][3]
    float*       __restrict__ out)     // [B][N][C][8]
{
    __shared__ __align__(16) float s_tile[4][32][33];
    __shared__ int   s_wcnt[8];
    __shared__ int   s_tots[8];        // all 8 segment counts of this box (DSMEM-filled)
    __shared__ int   s_bin[1032];
    __shared__ __align__(16) float s_red[8][128];

    const int g    = blockIdx.x;
    const int t    = threadIdx.x;
    const int lane = t & 31;
    const int w    = t >> 5;
    const int bn   = g >> 3;        // box (cluster id)
    const int k    = g & 7;         // bin == segment == cluster rank
    const int bb   = bn >> 5;       // batch of this box

    const int off0 = __ldg(offset + 0);
    const int off1 = __ldg(offset + 1);

    // ---- transpose: CTA g owns (b = g>>8, cblock = (g>>6)&3,
    //      p-blocks {(g&63) + 64*i}) -> strided over all 4 quarters ----
    const int bt   = g >> 8;
    const int c0   = ((g >> 6) & 3) * 32;
    const int pidx = g & 63;
    const int offt = bt ? off1 : off0;
    const int tx = t & 7, ty = t >> 3;

    int    pb[4];
    bool   keep[4];
    float4 v[4];
#pragma unroll
    for (int i = 0; i < 4; i++) {
        pb[i]   = (pidx + 64 * i) * 32;
        keep[i] = pb[i] < offt;                      // rows never referenced -> skip
        if (keep[i])
            v[i] = *(const float4*)(feat + (size_t)bt * Cx * Px
                                    + (size_t)(c0 + ty) * Px + pb[i] + tx * 4);
    }

    // ---- box params (uniform __ldg broadcast; RO inputs) ----
    const float bx0 = __ldg(boxes + bn * 6 + 0);
    const float by0 = __ldg(boxes + bn * 6 + 1);
    const float bz0 = __ldg(boxes + bn * 6 + 2);
    const float hx  = __ldg(boxes + bn * 6 + 3) * 0.5f;
    const float hy  = __ldg(boxes + bn * 6 + 4) * 0.5f;
    const float hz  = __ldg(boxes + bn * 6 + 5) * 0.5f;
    const float lox = bx0 - hx, hix = bx0 + hx;
    const float loy = by0 - hy, hiy = by0 + hy;
    const float loz = bz0 - hz, hiz = bz0 + hz;

    // ---- pc loads for segment k (overlap transpose latency) ----
    const int offb = bb ? off1 : off0;
    const float* pcb = pc + (size_t)bb * Px * 3;
    const int wseg = k * 1024 + w * 128;             // this warp's 128 points

    float qx[4], qy[4], qz[4];
#pragma unroll
    for (int i = 0; i < 4; i++) {
        const int p = wseg + i * 32 + lane;
        if (p < offb) {
            qx[i] = __ldg(pcb + p * 3 + 0);
            qy[i] = __ldg(pcb + p * 3 + 1);
            qz[i] = __ldg(pcb + p * 3 + 2);
        }
    }

    // ---- STS tiles ----
#pragma unroll
    for (int i = 0; i < 4; i++) {
        if (keep[i]) {
            s_tile[i][ty][tx * 4 + 0] = v[i].x;
            s_tile[i][ty][tx * 4 + 1] = v[i].y;
            s_tile[i][ty][tx * 4 + 2] = v[i].z;
            s_tile[i][ty][tx * 4 + 3] = v[i].w;
        }
    }

    // ---- flags + ballots ----
    unsigned bal[4];
    unsigned fl = 0;
    int cntw = 0;
#pragma unroll
    for (int i = 0; i < 4; i++) {
        const int p = wseg + i * 32 + lane;
        bool flag = false;
        if (p < offb)
            flag = (qx[i] >= lox) & (qx[i] <= hix) &
                   (qy[i] >= loy) & (qy[i] <= hiy) &
                   (qz[i] >= loz) & (qz[i] <= hiz);
        bal[i] = __ballot_sync(0xffffffffu, flag);
        fl |= ((unsigned)flag) << i;
        cntw += __popc(bal[i]);
    }
    if (lane == 0) s_wcnt[w] = cntw;

    __syncthreads();                                 // s_tile + s_wcnt ready

    // ---- featT stores (before fence; drain overlaps the rest) ----
    {
        const int cx = t & 7, py = t >> 3;
        float* dst = g_featT + (size_t)bt * Px * Cx + (size_t)py * Cx + c0 + cx * 4;
#pragma unroll
        for (int i = 0; i < 4; i++) {
            if (keep[i]) {
                float4 o;
                o.x = s_tile[i][cx * 4 + 0][py];
                o.y = s_tile[i][cx * 4 + 1][py];
                o.z = s_tile[i][cx * 4 + 2][py];
                o.w = s_tile[i][cx * 4 + 3][py];
                *(float4*)(dst + (size_t)pb[i] * Cx) = o;
            }
        }
    }

    // ---- per-warp prefix within segment ----
    int base = 0, tot = 0;
#pragma unroll
    for (int ww = 0; ww < 8; ww++) {
        if (ww < w) base += s_wcnt[ww];
        tot += s_wcnt[ww];
    }

    // ---- share tots across the 8-CTA cluster (slot k on every rank) ----
    const uint32_t tots_addr = smem_u32(&s_tots[k]);
    if (t < 8) st_shared_cluster_u32(tots_addr, t, tot);
    asm volatile("barrier.cluster.arrive.aligned;" ::: "memory");
    asm volatile("barrier.cluster.wait.aligned;"   ::: "memory");

    int ct[8];
#pragma unroll
    for (int s = 0; s < 8; s++) ct[s] = s_tots[s];
    int mybase = 0, cnt = 0;
#pragma unroll
    for (int s = 0; s < 8; s++) {
        if (s < k) mybase += ct[s];
        cnt += ct[s];
    }

    // ---- ordered writes into the BOX-GLOBAL list ----
    int* gl = g_list + bn * Px + mybase;
#pragma unroll
    for (int i = 0; i < 4; i++) {
        if ((fl >> i) & 1u)
            gl[base + __popc(bal[i] & ((1u << lane) - 1u))] = wseg + i * 32 + lane;
        base += __popc(bal[i]);
    }

    // bin bounds known pre-barrier (registers)
    const int st = (k * cnt) >> 3;                   // floor(k*cnt/8)
    const int en = ((k + 1) * cnt + 7) >> 3;         // ceil((k+1)*cnt/8)
    const int nb = en - st;                          // == 0 iff cnt == 0

    // ---- grid barrier: release fence + epoch flag (R15) ----
    __threadfence();           // RELEASE: publish featT + g_list
    __syncthreads();
    if (t == 0) {
        const unsigned a = atomicAdd(&g_bar, 1u);
        const unsigned epoch = a / GRIDX + 1u;
        if ((a + 1u) % GRIDX == 0u) {
            *(volatile unsigned*)&g_rel = epoch;
        } else {
            while (*(volatile unsigned*)&g_rel < epoch) __nanosleep(32);
        }
        __threadfence();       // ACQUIRE
    }
    __syncthreads();

    // ---- stage bin's indices: ONE contiguous coalesced read ----
    const int* src = g_list + bn * Px + st;
    for (int j = t; j < nb; j += 256) s_bin[j] = src[j];
    __syncthreads();

    // ---- gather max: 8 warps over points, lane = float4 channel group ----
    const float4* ftb = (const float4*)(g_featT + (size_t)bb * Px * Cx);
    float4 m = make_float4(NEGV, NEGV, NEGV, NEGV);
    for (int j = w; j < nb; j += 32) {               // batch-4 for MLP
        const int q0 = s_bin[j];
        const int q1 = (j + 8  < nb) ? s_bin[j + 8]  : q0;
        const int q2 = (j + 16 < nb) ? s_bin[j + 16] : q0;
        const int q3 = (j + 24 < nb) ? s_bin[j + 24] : q0;
        const float4 v0 = ftb[(size_t)q0 * 32 + lane];
        const float4 v1 = ftb[(size_t)q1 * 32 + lane];
        const float4 v2 = ftb[(size_t)q2 * 32 + lane];
        const float4 v3 = ftb[(size_t)q3 * 32 + lane];
        m.x = fmaxf(fmaxf(m.x, v0.x), fmaxf(fmaxf(v1.x, v2.x), v3.x));
        m.y = fmaxf(fmaxf(m.y, v0.y), fmaxf(fmaxf(v1.y, v2.y), v3.y));
        m.z = fmaxf(fmaxf(m.z, v0.z), fmaxf(fmaxf(v1.z, v2.z), v3.z));
        m.w = fmaxf(fmaxf(m.w, v0.w), fmaxf(fmaxf(v1.w, v2.w), v3.w));
    }
    *(float4*)&s_red[w][lane * 4] = m;
    __syncthreads();

    if (t < 128) {
        float r = s_red[0][t];
#pragma unroll
        for (int ww = 1; ww < 8; ww++) r = fmaxf(r, s_red[ww][t]);
        out[((size_t)bn * Cx + t) * G3x + k] = (cnt > 0) ? r : 0.0f;
    }
}

// ---------------------------------------------------------------------------
// Harness entry — single launch
// ---------------------------------------------------------------------------
extern "C" void kernel_launch(void* const* d_in, const int* in_sizes, int n_in,
                              void* d_out, int out_size)
{
    const float* boxes  = (const float*)d_in[0];   // (B, N, 6)
    const float* feat   = (const float*)d_in[1];   // (B, C, P)
    const int*   offset = (const int*)  d_in[2];   // (B,)
    const float* pc     = (const float*)d_in[3];   // (B, P, 3)
    float*       out    = (float*)d_out;           // (B, N, C, 2, 2, 2)

    roipool_fused_kernel<<<GRIDX, 256>>>(feat, boxes, offset, pc, out);
}